// round 1
// baseline (speedup 1.0000x reference)
#include <cuda_runtime.h>
#include <math.h>

#define NBATCH  16
#define NATOM   512
#define NEIGH   64
#define NPAIR   (NATOM*NEIGH)        /* 32768  */
#define TOTATOM (NBATCH*NATOM)       /* 8192   */
#define NPTOT   (NBATCH*NPAIR)       /* 524288 */
#define NWAVE   8
#define NL      13                   /* 1 + 3 + 9 angular rows */
#define NFEAT   104                  /* NL * NWAVE */
#define NORBIT  128
#define CAP     192                  /* bucket capacity per atom (mean 64, max ~94) */
#define NPAD    196                  /* padded pair stride (mult of 4, good banks)  */
#define GATOMS  16                   /* atoms per block in density kernel */

// Scratch: per-atom pair buckets (12 floats per record: dv.xyz, f_cut, R[0..7])
__device__ float d_bucket[(size_t)TOTATOM * CAP * 12];
__device__ int   d_cursor[TOTATOM];

// ---------------------------------------------------------------------------
// Kernel 1: per-pair geometry + radial, scattered into per-center-atom buckets
// ---------------------------------------------------------------------------
__global__ void k_pairs(const float* __restrict__ cart,
                        const int*   __restrict__ species,
                        const int*   __restrict__ atom_index,
                        const float* __restrict__ shifts,
                        const float* __restrict__ rs,
                        const float* __restrict__ inta,
                        const float* __restrict__ params,
                        const float* __restrict__ cutoff)
{
    int p = blockIdx.x * blockDim.x + threadIdx.x;
    if (p >= NPTOT) return;

    int b   = p / NPAIR;
    int off = b * NATOM;
    int i   = off + atom_index[p];              // center (segment id)
    int j   = off + atom_index[NPTOT + p];      // neighbor

    float dx = cart[3*i+0] - cart[3*j+0] + shifts[3*p+0];
    float dy = cart[3*i+1] - cart[3*j+1] + shifts[3*p+1];
    float dz = cart[3*i+2] - cart[3*j+2] + shifts[3*p+2];
    float d  = sqrtf(dx*dx + dy*dy + dz*dz);

    float fc = 0.5f * cosf(d * (3.14159265358979323846f / cutoff[0])) + 0.5f;
    fc *= fc;

    int sp = species[j];
    float R[NWAVE];
#pragma unroll
    for (int w = 0; w < NWAVE; ++w) {
        float t = d - rs[sp*NWAVE + w];
        R[w] = params[sp*NWAVE + w] * expf(inta[sp*NWAVE + w] * t * t);
    }

    int pos = atomicAdd(&d_cursor[i], 1);
    if (pos < CAP) {
        float4* rec = reinterpret_cast<float4*>(&d_bucket[((size_t)i*CAP + pos)*12]);
        rec[0] = make_float4(dx, dy, dz, fc);
        rec[1] = make_float4(R[0], R[1], R[2], R[3]);
        rec[2] = make_float4(R[4], R[5], R[6], R[7]);
    }
}

// ---------------------------------------------------------------------------
// Kernel 2: per-atom dense accumulation of sum_worb[13][8] + fused stage-2
//   density[atom][m] = sum_l ( sum_w sw[l][w] * hp[l][w][m] )^2
// hp kept in registers (thread = m); loaded once per block (GATOMS atoms).
// ---------------------------------------------------------------------------
__global__ void __launch_bounds__(128)
k_density(const float* __restrict__ hyper,      // (3, 8, 128)
          const int*   __restrict__ index_para, // (13,)
          float*       __restrict__ out)        // (8192, 128)
{
    __shared__ float Asm[NL   * NPAD];
    __shared__ float Rsm[NWAVE* NPAD];
    __shared__ float sw [NFEAT];

    const int t = threadIdx.x;            // orbit index m (0..127)

    // load hp[l][w][m] into registers for this m
    float hp[NFEAT];
#pragma unroll
    for (int l = 0; l < NL; ++l) {
        int ip = index_para[l];
#pragma unroll
        for (int w = 0; w < NWAVE; ++w)
            hp[l*NWAVE + w] = hyper[(ip*NWAVE + w)*NORBIT + t];
    }

    const int l_f = t >> 3;               // feature thread mapping (t < 104)
    const int w_f = t & 7;

    for (int g = 0; g < GATOMS; ++g) {
        const int atom = blockIdx.x * GATOMS + g;
        int n  = d_cursor[atom];
        if (n > CAP) n = CAP;
        const int n4 = (n + 3) & ~3;

        // ---- pass 1: build A (angular*fc) and R columns in SMEM ----
        for (int p = t; p < n4; p += 128) {
            float a[NL], r[NWAVE];
            if (p < n) {
                const float4* rec =
                    reinterpret_cast<const float4*>(&d_bucket[((size_t)atom*CAP + p)*12]);
                float4 v0 = rec[0], v1 = rec[1], v2 = rec[2];
                a[0]  = v0.w;
                a[1]  = v0.w * v0.x;  a[2]  = v0.w * v0.y;  a[3]  = v0.w * v0.z;
                a[4]  = a[1] * v0.x;  a[5]  = a[1] * v0.y;  a[6]  = a[1] * v0.z;
                a[7]  = a[2] * v0.x;  a[8]  = a[2] * v0.y;  a[9]  = a[2] * v0.z;
                a[10] = a[3] * v0.x;  a[11] = a[3] * v0.y;  a[12] = a[3] * v0.z;
                r[0]=v1.x; r[1]=v1.y; r[2]=v1.z; r[3]=v1.w;
                r[4]=v2.x; r[5]=v2.y; r[6]=v2.z; r[7]=v2.w;
            } else {
#pragma unroll
                for (int l = 0; l < NL; ++l)    a[l] = 0.f;
#pragma unroll
                for (int w = 0; w < NWAVE; ++w) r[w] = 0.f;
            }
#pragma unroll
            for (int l = 0; l < NL; ++l)    Asm[l*NPAD + p] = a[l];
#pragma unroll
            for (int w = 0; w < NWAVE; ++w) Rsm[w*NPAD + p] = r[w];
        }
        __syncthreads();

        // ---- pass 2: sum_worb[l][w] = sum_p A[l][p] * R[w][p] ----
        if (t < NFEAT) {
            float acc = 0.f;
            for (int p = 0; p < n4; p += 4) {
                float4 av = *reinterpret_cast<const float4*>(&Asm[l_f*NPAD + p]);
                float4 rv = *reinterpret_cast<const float4*>(&Rsm[w_f*NPAD + p]);
                acc += av.x*rv.x + av.y*rv.y + av.z*rv.z + av.w*rv.w;
            }
            sw[t] = acc;
        }
        __syncthreads();

        // ---- pass 3: density[atom][m] = sum_l (sum_w sw*hp)^2 ----
        float dens = 0.f;
#pragma unroll
        for (int l = 0; l < NL; ++l) {
            float h = 0.f;
#pragma unroll
            for (int w = 0; w < NWAVE; ++w)
                h += sw[l*NWAVE + w] * hp[l*NWAVE + w];
            dens += h * h;
        }
        out[(size_t)atom*NORBIT + t] = dens;
        __syncthreads();   // SMEM reuse for next atom
    }
}

// ---------------------------------------------------------------------------
extern "C" void kernel_launch(void* const* d_in, const int* in_sizes, int n_in,
                              void* d_out, int out_size)
{
    const float* cart    = (const float*)d_in[0];
    /* d_in[1] = numatoms (unused: all batches full) */
    const int*   species = (const int*)  d_in[2];
    const int*   aidx    = (const int*)  d_in[3];
    const float* shifts  = (const float*)d_in[4];
    const float* rs      = (const float*)d_in[5];
    const float* inta    = (const float*)d_in[6];
    const float* params  = (const float*)d_in[7];
    const float* hyper   = (const float*)d_in[8];
    const int*   ipara   = (const int*)  d_in[9];
    const float* cutoff  = (const float*)d_in[10];
    float*       out     = (float*)d_out;

    void* curp = nullptr;
    cudaGetSymbolAddress(&curp, d_cursor);
    cudaMemsetAsync(curp, 0, TOTATOM * sizeof(int));

    k_pairs<<<NPTOT/256, 256>>>(cart, species, aidx, shifts,
                                rs, inta, params, cutoff);
    k_density<<<TOTATOM/GATOMS, 128>>>(hyper, ipara, out);
}

// round 2
// speedup vs baseline: 1.4105x; 1.4105x over previous
#include <cuda_runtime.h>
#include <math.h>

#define NBATCH  16
#define NATOM   512
#define NEIGH   64
#define NPAIR   (NATOM*NEIGH)        /* 32768  */
#define TOTATOM (NBATCH*NATOM)       /* 8192   */
#define NPTOT   (NBATCH*NPAIR)       /* 524288 */
#define NWAVE   8
#define NL      13                   /* 1 + 3 + 9 angular rows */
#define NFEAT   104                  /* NL * NWAVE */
#define NORBIT  128
#define CAP     192                  /* bucket capacity per atom (mean 64, max ~94) */
#define NPAD    196                  /* padded pair stride */
#define GATOMS  16                   /* atoms per block in stage-2 kernel */

// Scratch: per-atom pair buckets (12 floats: dv.xyz, f_cut, R[0..7])
__device__ float d_bucket[(size_t)TOTATOM * CAP * 12];
__device__ int   d_cursor[TOTATOM];
__device__ float d_sw[(size_t)TOTATOM * NFEAT];   // sum_worb scratch

// ---------------------------------------------------------------------------
// Kernel 1: per-pair geometry + radial, scattered into per-center-atom buckets
// ---------------------------------------------------------------------------
__global__ void k_pairs(const float* __restrict__ cart,
                        const int*   __restrict__ species,
                        const int*   __restrict__ atom_index,
                        const float* __restrict__ shifts,
                        const float* __restrict__ rs,
                        const float* __restrict__ inta,
                        const float* __restrict__ params,
                        const float* __restrict__ cutoff)
{
    int p = blockIdx.x * blockDim.x + threadIdx.x;
    if (p >= NPTOT) return;

    int b   = p / NPAIR;
    int off = b * NATOM;
    int i   = off + atom_index[p];              // center (segment id)
    int j   = off + atom_index[NPTOT + p];      // neighbor

    float dx = cart[3*i+0] - cart[3*j+0] + shifts[3*p+0];
    float dy = cart[3*i+1] - cart[3*j+1] + shifts[3*p+1];
    float dz = cart[3*i+2] - cart[3*j+2] + shifts[3*p+2];
    float d  = sqrtf(dx*dx + dy*dy + dz*dz);

    float fc = 0.5f * cosf(d * (3.14159265358979323846f / cutoff[0])) + 0.5f;
    fc *= fc;

    int sp = species[j];
    float R[NWAVE];
#pragma unroll
    for (int w = 0; w < NWAVE; ++w) {
        float t = d - rs[sp*NWAVE + w];
        R[w] = params[sp*NWAVE + w] * expf(inta[sp*NWAVE + w] * t * t);
    }

    int pos = atomicAdd(&d_cursor[i], 1);
    if (pos < CAP) {
        float4* rec = reinterpret_cast<float4*>(&d_bucket[((size_t)i*CAP + pos)*12]);
        rec[0] = make_float4(dx, dy, dz, fc);
        rec[1] = make_float4(R[0], R[1], R[2], R[3]);
        rec[2] = make_float4(R[4], R[5], R[6], R[7]);
    }
}

// ---------------------------------------------------------------------------
// Kernel 2a: one block per atom -> sum_worb[13][8]  (high block-level
// parallelism, low regs, one barrier per block)
// ---------------------------------------------------------------------------
__global__ void __launch_bounds__(128)
k_accum(float* __restrict__ swout)
{
    __shared__ float Asm[NL    * NPAD];
    __shared__ float Rsm[NWAVE * NPAD];

    const int atom = blockIdx.x;
    const int t    = threadIdx.x;

    int n = d_cursor[atom];
    if (n > CAP) n = CAP;
    const int n4 = (n + 3) & ~3;

    // pass 1: expand records into A (angular*fc) and R columns in SMEM
    for (int p = t; p < n4; p += 128) {
        float a[NL], r[NWAVE];
        if (p < n) {
            const float4* rec =
                reinterpret_cast<const float4*>(&d_bucket[((size_t)atom*CAP + p)*12]);
            float4 v0 = rec[0], v1 = rec[1], v2 = rec[2];
            a[0]  = v0.w;
            a[1]  = v0.w * v0.x;  a[2]  = v0.w * v0.y;  a[3]  = v0.w * v0.z;
            a[4]  = a[1] * v0.x;  a[5]  = a[1] * v0.y;  a[6]  = a[1] * v0.z;
            a[7]  = a[2] * v0.x;  a[8]  = a[2] * v0.y;  a[9]  = a[2] * v0.z;
            a[10] = a[3] * v0.x;  a[11] = a[3] * v0.y;  a[12] = a[3] * v0.z;
            r[0]=v1.x; r[1]=v1.y; r[2]=v1.z; r[3]=v1.w;
            r[4]=v2.x; r[5]=v2.y; r[6]=v2.z; r[7]=v2.w;
        } else {
#pragma unroll
            for (int l = 0; l < NL; ++l)    a[l] = 0.f;
#pragma unroll
            for (int w = 0; w < NWAVE; ++w) r[w] = 0.f;
        }
#pragma unroll
        for (int l = 0; l < NL; ++l)    Asm[l*NPAD + p] = a[l];
#pragma unroll
        for (int w = 0; w < NWAVE; ++w) Rsm[w*NPAD + p] = r[w];
    }
    __syncthreads();

    // pass 2: sw[l][w] = sum_p A[l][p]*R[w][p]
    if (t < NFEAT) {
        const int l_f = t >> 3;
        const int w_f = t & 7;
        float acc = 0.f;
        for (int p = 0; p < n4; p += 4) {
            float4 av = *reinterpret_cast<const float4*>(&Asm[l_f*NPAD + p]);
            float4 rv = *reinterpret_cast<const float4*>(&Rsm[w_f*NPAD + p]);
            acc += av.x*rv.x + av.y*rv.y + av.z*rv.z + av.w*rv.w;
        }
        swout[(size_t)atom*NFEAT + t] = acc;
    }
}

// ---------------------------------------------------------------------------
// Kernel 2b: density[atom][m] = sum_l ( sum_w sw[l][w]*hp[l][w][m] )^2
// thread = m; hp in registers; one barrier per block; pure FFMA inner loops.
// ---------------------------------------------------------------------------
__global__ void __launch_bounds__(128)
k_stage2(const float* __restrict__ hyper,      // (3, 8, 128)
         const int*   __restrict__ index_para, // (13,)
         const float* __restrict__ sw,         // (8192, 104)
         float*       __restrict__ out)        // (8192, 128)
{
    const int t = threadIdx.x;

    float hp[NFEAT];
#pragma unroll
    for (int l = 0; l < NL; ++l) {
        int ip = index_para[l];
#pragma unroll
        for (int w = 0; w < NWAVE; ++w)
            hp[l*NWAVE + w] = hyper[(ip*NWAVE + w)*NORBIT + t];
    }

    __shared__ float swsm[GATOMS * NFEAT];
    const int base = blockIdx.x * GATOMS;

    // cooperative coalesced load of 16 atoms' sw
    for (int i = t; i < GATOMS * NFEAT; i += 128)
        swsm[i] = sw[(size_t)base * NFEAT + i];
    __syncthreads();

#pragma unroll 2
    for (int g = 0; g < GATOMS; ++g) {
        const float* s = &swsm[g * NFEAT];
        float dens = 0.f;
#pragma unroll
        for (int l = 0; l < NL; ++l) {
            float h = 0.f;
#pragma unroll
            for (int w = 0; w < NWAVE; ++w)
                h += s[l*NWAVE + w] * hp[l*NWAVE + w];
            dens += h * h;
        }
        out[(size_t)(base + g)*NORBIT + t] = dens;
    }
}

// ---------------------------------------------------------------------------
extern "C" void kernel_launch(void* const* d_in, const int* in_sizes, int n_in,
                              void* d_out, int out_size)
{
    const float* cart    = (const float*)d_in[0];
    /* d_in[1] = numatoms (unused: all batches full) */
    const int*   species = (const int*)  d_in[2];
    const int*   aidx    = (const int*)  d_in[3];
    const float* shifts  = (const float*)d_in[4];
    const float* rs      = (const float*)d_in[5];
    const float* inta    = (const float*)d_in[6];
    const float* params  = (const float*)d_in[7];
    const float* hyper   = (const float*)d_in[8];
    const int*   ipara   = (const int*)  d_in[9];
    const float* cutoff  = (const float*)d_in[10];
    float*       out     = (float*)d_out;

    void* curp = nullptr;
    cudaGetSymbolAddress(&curp, d_cursor);
    cudaMemsetAsync(curp, 0, TOTATOM * sizeof(int));

    void* swp = nullptr;
    cudaGetSymbolAddress(&swp, d_sw);

    k_pairs<<<NPTOT/256, 256>>>(cart, species, aidx, shifts,
                                rs, inta, params, cutoff);
    k_accum<<<TOTATOM, 128>>>((float*)swp);
    k_stage2<<<TOTATOM/GATOMS, 128>>>(hyper, ipara, (const float*)swp, out);
}

// round 3
// speedup vs baseline: 1.5643x; 1.1091x over previous
#include <cuda_runtime.h>
#include <math.h>

#define NBATCH  16
#define NATOM   512
#define NEIGH   64
#define NPAIR   (NATOM*NEIGH)        /* 32768  */
#define TOTATOM (NBATCH*NATOM)       /* 8192   */
#define NPTOT   (NBATCH*NPAIR)       /* 524288 */
#define NWAVE   8
#define NL      13
#define NFEAT   104                  /* NL * NWAVE */
#define NORBIT  128
#define CAP     192                  /* bucket capacity per atom (mean 64) */
#define GATOMS  16

// Scratch: per-atom pair buckets (12 floats: dv.xyz, f_cut, R[0..7])
__device__ float d_bucket[(size_t)TOTATOM * CAP * 12];
__device__ int   d_cursor[TOTATOM];            // zero-init; self-cleaned by k_accum
__device__ float d_sw[(size_t)TOTATOM * NFEAT];

// ---------------------------------------------------------------------------
// Kernel 1: per-pair geometry + radial -> per-center-atom buckets.
// One block handles 512 pairs of ONE batch; cart/species/tables staged in SMEM.
// ---------------------------------------------------------------------------
__global__ void __launch_bounds__(256)
k_pairs(const float* __restrict__ cart,
        const int*   __restrict__ species,
        const int*   __restrict__ atom_index,
        const float* __restrict__ shifts,
        const float* __restrict__ rs,
        const float* __restrict__ inta,
        const float* __restrict__ params,
        const float* __restrict__ cutoff)
{
    __shared__ float scart[NATOM * 3];
    __shared__ int   ssp  [NATOM];
    __shared__ float stab [96];      // [0:32) rs, [32:64) inta, [64:96) params

    const int b   = blockIdx.y;
    const int tid = threadIdx.x;

    const float* cb = cart + (size_t)b * NATOM * 3;
    for (int i = tid; i < NATOM * 3; i += 256) scart[i] = cb[i];
    for (int i = tid; i < NATOM;     i += 256) ssp[i]   = species[b * NATOM + i];
    if (tid < 32) {
        stab[tid]      = rs[tid];
        stab[32 + tid] = inta[tid];
        stab[64 + tid] = params[tid];
    }
    const float inv_cut_pi = 3.14159265358979323846f / cutoff[0];
    __syncthreads();

#pragma unroll
    for (int u = 0; u < 2; ++u) {
        const int p_loc = blockIdx.x * 512 + u * 256 + tid;
        const int p     = b * NPAIR + p_loc;

        const int i_loc = atom_index[p];
        const int j_loc = atom_index[NPTOT + p];

        float dx = scart[3*i_loc+0] - scart[3*j_loc+0] + shifts[3*p+0];
        float dy = scart[3*i_loc+1] - scart[3*j_loc+1] + shifts[3*p+1];
        float dz = scart[3*i_loc+2] - scart[3*j_loc+2] + shifts[3*p+2];
        float d  = sqrtf(dx*dx + dy*dy + dz*dz);

        float c  = __cosf(d * inv_cut_pi);
        float fc = 0.5f * c + 0.5f;
        fc *= fc;

        const int sp = ssp[j_loc];
        const float4 rs_lo = *reinterpret_cast<const float4*>(&stab[sp*8]);
        const float4 rs_hi = *reinterpret_cast<const float4*>(&stab[sp*8+4]);
        const float4 a_lo  = *reinterpret_cast<const float4*>(&stab[32+sp*8]);
        const float4 a_hi  = *reinterpret_cast<const float4*>(&stab[32+sp*8+4]);
        const float4 p_lo  = *reinterpret_cast<const float4*>(&stab[64+sp*8]);
        const float4 p_hi  = *reinterpret_cast<const float4*>(&stab[64+sp*8+4]);

        float R[NWAVE];
        {
            float t;
            t = d - rs_lo.x; R[0] = p_lo.x * __expf(a_lo.x * t * t);
            t = d - rs_lo.y; R[1] = p_lo.y * __expf(a_lo.y * t * t);
            t = d - rs_lo.z; R[2] = p_lo.z * __expf(a_lo.z * t * t);
            t = d - rs_lo.w; R[3] = p_lo.w * __expf(a_lo.w * t * t);
            t = d - rs_hi.x; R[4] = p_hi.x * __expf(a_hi.x * t * t);
            t = d - rs_hi.y; R[5] = p_hi.y * __expf(a_hi.y * t * t);
            t = d - rs_hi.z; R[6] = p_hi.z * __expf(a_hi.z * t * t);
            t = d - rs_hi.w; R[7] = p_hi.w * __expf(a_hi.w * t * t);
        }

        const int i_glob = b * NATOM + i_loc;
        int pos = atomicAdd(&d_cursor[i_glob], 1);
        if (pos < CAP) {
            float4* rec = reinterpret_cast<float4*>(
                &d_bucket[((size_t)i_glob * CAP + pos) * 12]);
            rec[0] = make_float4(dx, dy, dz, fc);
            rec[1] = make_float4(R[0], R[1], R[2], R[3]);
            rec[2] = make_float4(R[4], R[5], R[6], R[7]);
        }
    }
}

// ---------------------------------------------------------------------------
// Kernel 2a: block per atom -> sw[13][8].
// thread = (w, pair-slice): 8 w-groups x 16 slices; 13 register accumulators.
// Self-cleans d_cursor for the next graph replay.
// ---------------------------------------------------------------------------
__global__ void __launch_bounds__(128)
k_accum(float* __restrict__ swout)
{
    __shared__ float4 recs[CAP * 3];          // raw records
    __shared__ float  red [NL * 128];         // reduction buffer

    const int atom = blockIdx.x;
    const int t    = threadIdx.x;
    const int w    = t & 7;
    const int sl   = t >> 3;                  // 0..15

    int n = d_cursor[atom];
    if (n > CAP) n = CAP;

    const float4* src = reinterpret_cast<const float4*>(
        &d_bucket[(size_t)atom * CAP * 12]);
    for (int i = t; i < 3 * n; i += 128) recs[i] = src[i];
    __syncthreads();
    if (t == 0) d_cursor[atom] = 0;           // self-clean

    float acc[NL];
#pragma unroll
    for (int l = 0; l < NL; ++l) acc[l] = 0.f;

    const float* recf = reinterpret_cast<const float*>(recs);
    for (int p = sl; p < n; p += 16) {
        float4 v0 = recs[3 * p];
        float  r  = recf[12 * p + 4 + w];
        float  q  = v0.w * r;                 // fc * r
        float  qx = q * v0.x, qy = q * v0.y, qz = q * v0.z;
        acc[0]  += q;
        acc[1]  += qx;        acc[2]  += qy;        acc[3]  += qz;
        acc[4]  += qx * v0.x; acc[5]  += qx * v0.y; acc[6]  += qx * v0.z;
        acc[7]  += qy * v0.x; acc[8]  += qy * v0.y; acc[9]  += qy * v0.z;
        acc[10] += qz * v0.x; acc[11] += qz * v0.y; acc[12] += qz * v0.z;
    }

#pragma unroll
    for (int l = 0; l < NL; ++l) red[l * 128 + t] = acc[l];
    __syncthreads();

    if (t < NFEAT) {
        const int l_f = t >> 3;
        const int w_f = t & 7;
        float s = 0.f;
#pragma unroll
        for (int k = 0; k < 16; ++k)
            s += red[l_f * 128 + k * 8 + w_f];
        swout[(size_t)atom * NFEAT + t] = s;
    }
}

// ---------------------------------------------------------------------------
// Kernel 2b: density[atom][m] = sum_l ( sum_w sw[l][w]*hp[l][w][m] )^2
// ---------------------------------------------------------------------------
__global__ void __launch_bounds__(128)
k_stage2(const float* __restrict__ hyper,      // (3, 8, 128)
         const int*   __restrict__ index_para, // (13,)
         const float* __restrict__ sw,         // (8192, 104)
         float*       __restrict__ out)        // (8192, 128)
{
    const int t = threadIdx.x;

    float hp[NFEAT];
#pragma unroll
    for (int l = 0; l < NL; ++l) {
        int ip = index_para[l];
#pragma unroll
        for (int w = 0; w < NWAVE; ++w)
            hp[l*NWAVE + w] = hyper[(ip*NWAVE + w)*NORBIT + t];
    }

    __shared__ float swsm[GATOMS * NFEAT];
    const int base = blockIdx.x * GATOMS;

    for (int i = t; i < GATOMS * NFEAT; i += 128)
        swsm[i] = sw[(size_t)base * NFEAT + i];
    __syncthreads();

#pragma unroll 2
    for (int g = 0; g < GATOMS; ++g) {
        const float* s = &swsm[g * NFEAT];
        float dens = 0.f;
#pragma unroll
        for (int l = 0; l < NL; ++l) {
            float h = 0.f;
#pragma unroll
            for (int w = 0; w < NWAVE; ++w)
                h += s[l*NWAVE + w] * hp[l*NWAVE + w];
            dens += h * h;
        }
        out[(size_t)(base + g)*NORBIT + t] = dens;
    }
}

// ---------------------------------------------------------------------------
extern "C" void kernel_launch(void* const* d_in, const int* in_sizes, int n_in,
                              void* d_out, int out_size)
{
    const float* cart    = (const float*)d_in[0];
    const int*   species = (const int*)  d_in[2];
    const int*   aidx    = (const int*)  d_in[3];
    const float* shifts  = (const float*)d_in[4];
    const float* rs      = (const float*)d_in[5];
    const float* inta    = (const float*)d_in[6];
    const float* params  = (const float*)d_in[7];
    const float* hyper   = (const float*)d_in[8];
    const int*   ipara   = (const int*)  d_in[9];
    const float* cutoff  = (const float*)d_in[10];
    float*       out     = (float*)d_out;

    void* swp = nullptr;
    cudaGetSymbolAddress(&swp, d_sw);

    dim3 pgrid(NPAIR / 512, NBATCH);
    k_pairs<<<pgrid, 256>>>(cart, species, aidx, shifts,
                            rs, inta, params, cutoff);
    k_accum<<<TOTATOM, 128>>>((float*)swp);
    k_stage2<<<TOTATOM / GATOMS, 128>>>(hyper, ipara, (const float*)swp, out);
}

// round 4
// speedup vs baseline: 1.7652x; 1.1284x over previous
#include <cuda_runtime.h>
#include <math.h>

#define NBATCH  16
#define NATOM   512
#define NEIGH   64
#define NPAIR   (NATOM*NEIGH)        /* 32768  */
#define TOTATOM (NBATCH*NATOM)       /* 8192   */
#define NPTOT   (NBATCH*NPAIR)       /* 524288 */
#define NWAVE   8
#define NL      13
#define NFEAT   104                  /* NL * NWAVE */
#define NORBIT  128
#define CAP     192                  /* bucket capacity per atom (mean 64) */
#define GATOMS  16

// Scratch: per-atom pair buckets, 16B records: (dx, dy, dz, species_j bits)
__device__ float4 d_rec[(size_t)TOTATOM * CAP];
__device__ int    d_cursor[TOTATOM];           // zero-init; self-cleaned by k_accum
__device__ float  d_sw[(size_t)TOTATOM * NFEAT];

// ---------------------------------------------------------------------------
// Kernel 1: minimal per-pair kernel: displacement vector + species, bucketed.
// ---------------------------------------------------------------------------
__global__ void __launch_bounds__(256)
k_pairs(const float* __restrict__ cart,
        const int*   __restrict__ species,
        const int*   __restrict__ atom_index,
        const float* __restrict__ shifts)
{
    __shared__ float scart[NATOM * 3];
    __shared__ int   ssp  [NATOM];

    const int b   = blockIdx.y;
    const int tid = threadIdx.x;

    const float* cb = cart + (size_t)b * NATOM * 3;
    for (int i = tid; i < NATOM * 3; i += 256) scart[i] = cb[i];
    for (int i = tid; i < NATOM;     i += 256) ssp[i]   = species[b * NATOM + i];
    __syncthreads();

#pragma unroll
    for (int u = 0; u < 2; ++u) {
        const int p_loc = blockIdx.x * 512 + u * 256 + tid;
        const int p     = b * NPAIR + p_loc;

        const int i_loc = atom_index[p];
        const int j_loc = atom_index[NPTOT + p];

        float dx = scart[3*i_loc+0] - scart[3*j_loc+0] + shifts[3*p+0];
        float dy = scart[3*i_loc+1] - scart[3*j_loc+1] + shifts[3*p+1];
        float dz = scart[3*i_loc+2] - scart[3*j_loc+2] + shifts[3*p+2];

        const int i_glob = b * NATOM + i_loc;
        int pos = atomicAdd(&d_cursor[i_glob], 1);
        if (pos < CAP) {
            d_rec[(size_t)i_glob * CAP + pos] =
                make_float4(dx, dy, dz, __int_as_float(ssp[j_loc]));
        }
    }
}

// ---------------------------------------------------------------------------
// Kernel 2a: block per atom -> sw[13][8].
// Phase A: per-pair (d, fc) once. Phase B: thread=(w, slice), radial recompute
// (one exp per thread per pair) + 13 register accumulators + SMEM reduction.
// ---------------------------------------------------------------------------
__global__ void __launch_bounds__(128)
k_accum(const float* __restrict__ rs,
        const float* __restrict__ inta,
        const float* __restrict__ params,
        const float* __restrict__ cutoff,
        float*       __restrict__ swout)
{
    __shared__ float4 recs[CAP];
    __shared__ float2 dfc [CAP];
    __shared__ float  stab[96];      // [0:32) rs, [32:64) inta, [64:96) params
    __shared__ float  red [NL * 128];

    const int atom = blockIdx.x;
    const int t    = threadIdx.x;

    if (t < 32) {
        stab[t]      = rs[t];
        stab[32 + t] = inta[t];
        stab[64 + t] = params[t];
    }

    int n = d_cursor[atom];
    if (n > CAP) n = CAP;

    const float4* src = &d_rec[(size_t)atom * CAP];
    for (int i = t; i < n; i += 128) recs[i] = src[i];
    __syncthreads();
    if (t == 0) d_cursor[atom] = 0;           // self-clean for next replay

    // Phase A: per-pair distance + cutoff (each pair handled by one thread)
    const float icp = 3.14159265358979323846f / cutoff[0];
    for (int p = t; p < n; p += 128) {
        float4 v = recs[p];
        float d  = sqrtf(v.x*v.x + v.y*v.y + v.z*v.z);
        float c  = 0.5f * __cosf(d * icp) + 0.5f;
        dfc[p]   = make_float2(d, c * c);
    }
    __syncthreads();

    // Phase B
    const int w  = t & 7;
    const int sl = t >> 3;                    // 0..15

    float acc[NL];
#pragma unroll
    for (int l = 0; l < NL; ++l) acc[l] = 0.f;

    for (int p = sl; p < n; p += 16) {
        float4 v  = recs[p];                  // broadcast within w-group
        float2 df = dfc[p];                   // broadcast within w-group
        int   sp  = __float_as_int(v.w);
        float tt  = df.x - stab[sp*8 + w];
        float r   = stab[64 + sp*8 + w] * __expf(stab[32 + sp*8 + w] * tt * tt);
        float q   = df.y * r;                 // fc * r
        float qx = q * v.x, qy = q * v.y, qz = q * v.z;
        acc[0]  += q;
        acc[1]  += qx;        acc[2]  += qy;        acc[3]  += qz;
        acc[4]  += qx * v.x;  acc[5]  += qx * v.y;  acc[6]  += qx * v.z;
        acc[7]  += qy * v.x;  acc[8]  += qy * v.y;  acc[9]  += qy * v.z;
        acc[10] += qz * v.x;  acc[11] += qz * v.y;  acc[12] += qz * v.z;
    }

#pragma unroll
    for (int l = 0; l < NL; ++l) red[l * 128 + t] = acc[l];
    __syncthreads();

    if (t < NFEAT) {
        const int l_f = t >> 3;
        const int w_f = t & 7;
        float s = 0.f;
#pragma unroll
        for (int k = 0; k < 16; ++k)
            s += red[l_f * 128 + k * 8 + w_f];
        swout[(size_t)atom * NFEAT + t] = s;
    }
}

// ---------------------------------------------------------------------------
// Kernel 2b: density[atom][m] = sum_l ( sum_w sw[l][w]*hp[l][w][m] )^2
// ---------------------------------------------------------------------------
__global__ void __launch_bounds__(128)
k_stage2(const float* __restrict__ hyper,      // (3, 8, 128)
         const int*   __restrict__ index_para, // (13,)
         const float* __restrict__ sw,         // (8192, 104)
         float*       __restrict__ out)        // (8192, 128)
{
    const int t = threadIdx.x;

    float hp[NFEAT];
#pragma unroll
    for (int l = 0; l < NL; ++l) {
        int ip = index_para[l];
#pragma unroll
        for (int w = 0; w < NWAVE; ++w)
            hp[l*NWAVE + w] = hyper[(ip*NWAVE + w)*NORBIT + t];
    }

    __shared__ float swsm[GATOMS * NFEAT];
    const int base = blockIdx.x * GATOMS;

    for (int i = t; i < GATOMS * NFEAT; i += 128)
        swsm[i] = sw[(size_t)base * NFEAT + i];
    __syncthreads();

#pragma unroll 2
    for (int g = 0; g < GATOMS; ++g) {
        const float* s = &swsm[g * NFEAT];
        float dens = 0.f;
#pragma unroll
        for (int l = 0; l < NL; ++l) {
            float h = 0.f;
#pragma unroll
            for (int w = 0; w < NWAVE; ++w)
                h += s[l*NWAVE + w] * hp[l*NWAVE + w];
            dens += h * h;
        }
        out[(size_t)(base + g)*NORBIT + t] = dens;
    }
}

// ---------------------------------------------------------------------------
extern "C" void kernel_launch(void* const* d_in, const int* in_sizes, int n_in,
                              void* d_out, int out_size)
{
    const float* cart    = (const float*)d_in[0];
    const int*   species = (const int*)  d_in[2];
    const int*   aidx    = (const int*)  d_in[3];
    const float* shifts  = (const float*)d_in[4];
    const float* rs      = (const float*)d_in[5];
    const float* inta    = (const float*)d_in[6];
    const float* params  = (const float*)d_in[7];
    const float* hyper   = (const float*)d_in[8];
    const int*   ipara   = (const int*)  d_in[9];
    const float* cutoff  = (const float*)d_in[10];
    float*       out     = (float*)d_out;

    void* swp = nullptr;
    cudaGetSymbolAddress(&swp, d_sw);

    dim3 pgrid(NPAIR / 512, NBATCH);
    k_pairs<<<pgrid, 256>>>(cart, species, aidx, shifts);
    k_accum<<<TOTATOM, 128>>>(rs, inta, params, cutoff, (float*)swp);
    k_stage2<<<TOTATOM / GATOMS, 128>>>(hyper, ipara, (const float*)swp, out);
}